// round 5
// baseline (speedup 1.0000x reference)
#include <cuda_runtime.h>

#define NPB 15   // prob bins
#define NC  8    // classes
#define NNB 9    // neighbor bins (3x3)
#define HH  512
#define WW  512
#define TX  32
#define TY  16
#define NTHREADS (TX*TY)
#define HW  (TX + 2)   // 34 halo width
#define HHALO (TY + 2) // 18 halo height

__device__ __forceinline__ float4 f4add(float4 a, float4 b) {
    return make_float4(a.x + b.x, a.y + b.y, a.z + b.z, a.w + b.w);
}

// XOR-swizzled pixel-major storage: pixel pix owns two 16B chunks at
// u = pix*2 (+h), swizzled u^((pix>>2)&1). Lane-consecutive pixels ->
// all 8 bank-groups covered -> conflict-free LDS.128/STS.128.
__device__ __forceinline__ void pix_st(float4* base, int pix, float4 a, float4 b) {
    const int u = pix * 2, sw = (pix >> 2) & 1;
    base[u ^ sw] = a;
    base[(u + 1) ^ sw] = b;
}
__device__ __forceinline__ void pix_ld(const float4* base, int pix, float4& a, float4& b) {
    const int u = pix * 2, sw = (pix >> 2) & 1;
    a = base[u ^ sw];
    b = base[(u + 1) ^ sw];
}

__global__ __launch_bounds__(NTHREADS, 4) void nectar_kernel(
    const float* __restrict__ logits,
    const float* __restrict__ vf,
    float* __restrict__ out)
{
    __shared__ float4 s_probs4[HHALO * HW * 2];  // 612 px * 32B = 19.6 KB
    __shared__ float4 s_col4[TY * HW * 2];       // 544 px * 32B = 17.4 KB
    __shared__ float  s_vf[NC * NNB * NPB];      // 4.3 KB

    const int t  = threadIdx.y * TX + threadIdx.x;
    const int b  = blockIdx.z;
    const int bx = blockIdx.x * TX;
    const int by = blockIdx.y * TY;

    for (int i = t; i < NC * NNB * NPB; i += NTHREADS) s_vf[i] = vf[i];

    const long plane = (long)HH * WW;
    const float* lbase = logits + (long)b * NC * plane;

    // Stage 1: halo softmax -> smem probs (zeros outside image = SAME/zero pad)
    for (int i = t; i < HHALO * HW; i += NTHREADS) {
        const int hy = i / HW;
        const int hx = i - hy * HW;
        const int gy = by + hy - 1;
        const int gx = bx + hx - 1;
        float4 a, c;
        if (gy >= 0 && gy < HH && gx >= 0 && gx < WW) {
            float v[NC];
            const float* p0 = lbase + (long)gy * WW + gx;
#pragma unroll
            for (int k = 0; k < NC; k++) v[k] = p0[k * plane];
            float m01 = fmaxf(v[0], v[1]), m23 = fmaxf(v[2], v[3]);
            float m45 = fmaxf(v[4], v[5]), m67 = fmaxf(v[6], v[7]);
            const float m = fmaxf(fmaxf(m01, m23), fmaxf(m45, m67));
#pragma unroll
            for (int k = 0; k < NC; k++) v[k] = __expf(v[k] - m);
            const float s = ((v[0] + v[1]) + (v[2] + v[3]))
                          + ((v[4] + v[5]) + (v[6] + v[7]));
            const float inv = __frcp_rn(s);
            a = make_float4(v[0] * inv, v[1] * inv, v[2] * inv, v[3] * inv);
            c = make_float4(v[4] * inv, v[5] * inv, v[6] * inv, v[7] * inv);
        } else {
            a = make_float4(0.f, 0.f, 0.f, 0.f);
            c = a;
        }
        pix_st(s_probs4, i, a, c);
    }
    __syncthreads();

    // Stage 2: vertical 3-sum (separable box filter, pass 1)
    for (int i = t; i < TY * HW; i += NTHREADS) {
        float4 a0, b0, a1, b1, a2, b2;
        pix_ld(s_probs4, i,          a0, b0);
        pix_ld(s_probs4, i + HW,     a1, b1);
        pix_ld(s_probs4, i + 2 * HW, a2, b2);
        pix_st(s_col4, i, f4add(f4add(a0, a1), a2), f4add(f4add(b0, b1), b2));
    }
    __syncthreads();

    // Stage 3: horizontal 3-sum, binning, gather, normalize, store
    const int tx = threadIdx.x;
    const int ty = threadIdx.y;
    const int gx = bx + tx;
    const int gy = by + ty;

    float4 pa, pb;
    pix_ld(s_probs4, (ty + 1) * HW + (tx + 1), pa, pb);
    float4 c0a, c0b, c1a, c1b, c2a, c2b;
    const int ci = ty * HW + tx;
    pix_ld(s_col4, ci,     c0a, c0b);
    pix_ld(s_col4, ci + 1, c1a, c1b);
    pix_ld(s_col4, ci + 2, c2a, c2b);
    const float4 na = f4add(f4add(c0a, c1a), c2a);
    const float4 nb = f4add(f4add(c0b, c1b), c2b);

    const float pn[NC] = {na.x, na.y, na.z, na.w, nb.x, nb.y, nb.z, nb.w};
    const float pp[NC] = {pa.x, pa.y, pa.z, pa.w, pb.x, pb.y, pb.z, pb.w};

    float f[NC];
    bool need = false;
#pragma unroll
    for (int c = 0; c < NC; c++) {
        const float s9 = pn[c];
        // fast path: floor(RN(RN(s/9)*9)) == floor(s) unless s is within
        // ~2.5 ulp of an integer; 1e-5 window guards the rare exact path.
        const int ib = (int)s9;                 // trunc == floor (s9 >= 0)
        const float fr = s9 - (float)ib;
        need |= (fr < 1e-5f) | (fr > 0.99999f);
        const int lbn = min(ib, NNB - 1);
        const int pbn = min((int)(pp[c] * 15.0f), NPB - 1);   // p >= 0
        f[c] = s_vf[c * (NNB * NPB) + lbn * NPB + pbn];
    }
    if (need) {   // rare: replicate the reference's double rounding exactly
#pragma unroll
        for (int c = 0; c < NC; c++) {
            int lbn = (int)floorf(__fmul_rn(__fdiv_rn(pn[c], 9.0f), 9.0f));
            lbn = max(0, min(lbn, NNB - 1));
            const int pbn = min((int)(pp[c] * 15.0f), NPB - 1);
            f[c] = s_vf[c * (NNB * NPB) + lbn * NPB + pbn];
        }
    }
    float s = ((f[0] + f[1]) + (f[2] + f[3])) + ((f[4] + f[5]) + (f[6] + f[7]));
    if (s == 0.f) s = 1.f;
    const float invs = __frcp_rn(s);   // continuous path: no binning downstream

    float* obase = out + (long)b * NC * plane + (long)gy * WW + gx;
#pragma unroll
    for (int c = 0; c < NC; c++)
        obase[c * plane] = f[c] * invs;
}

extern "C" void kernel_launch(void* const* d_in, const int* in_sizes, int n_in,
                              void* d_out, int out_size)
{
    const float* logits = (const float*)d_in[0];
    const float* vf     = (const float*)d_in[1];
    float* out          = (float*)d_out;

    dim3 block(TX, TY);
    dim3 grid(WW / TX, HH / TY, 16 /*B*/);
    nectar_kernel<<<grid, block>>>(logits, vf, out);
}